// round 6
// baseline (speedup 1.0000x reference)
#include <cuda_runtime.h>

#define N_NODES 100000
#define N_EDGES 600000
#define IN_DIM  6
#define HID     128
#define EPS     1e-5f

// ---------------- scratch (device globals: allocation-free) ----------------
// 16B alignment so float4 access is always legal.
__device__ __align__(16) float g_deg[N_NODES];            // degree -> inv_deg in place
__device__ __align__(16) float g_agg0[N_NODES * IN_DIM];  // layer-0 neighbor sums (6-dim)
__device__ __align__(16) float g_h0[N_NODES * HID];       // layer-0 out -> BN+ReLU in place
__device__ __align__(16) float g_agg1[N_NODES * HID];     // layer-1 neighbor sums
__device__ __align__(16) float g_h1[N_NODES * HID];       // layer-1 out -> BN+ReLU in place
__device__ __align__(16) float g_sum[HID];                // BN partial sums
__device__ __align__(16) float g_sq[HID];
__device__ __align__(16) float g_scale[HID];              // BN affine
__device__ __align__(16) float g_shift[HID];
__device__ __align__(16) float g_pl[N_NODES];             // layer-2 projections
__device__ __align__(16) float g_pr[N_NODES];
__device__ __align__(16) float g_acc2[N_NODES];           // layer-2 scalar aggregation

// ---------------- zero scratch (kernel launches only; no memset API) ----------------
__global__ void k_zero_big() {
    int i = blockIdx.x * blockDim.x + threadIdx.x;
    int stride = gridDim.x * blockDim.x;
    for (int j = i; j < N_NODES * (HID / 4); j += stride)
        ((float4*)g_agg1)[j] = make_float4(0.f, 0.f, 0.f, 0.f);
    for (int j = i; j < N_NODES * IN_DIM; j += stride) g_agg0[j] = 0.0f;
    for (int j = i; j < N_NODES; j += stride) { g_deg[j] = 0.0f; g_acc2[j] = 0.0f; }
    if (i < HID) { g_sum[i] = 0.0f; g_sq[i] = 0.0f; }
}

__global__ void k_zero_bn() {
    g_sum[threadIdx.x] = 0.0f;
    g_sq[threadIdx.x] = 0.0f;
}

// ---------------- degree ----------------
// edge_index is int32 on device (JAX default x64-disabled demotes int64 -> int32).
__global__ void k_deg(const int* __restrict__ ei) {
    int e = blockIdx.x * blockDim.x + threadIdx.x;
    if (e < N_EDGES) {
        int d = ei[N_EDGES + e];
        atomicAdd(&g_deg[d], 1.0f);
    }
}

__global__ void k_invdeg() {
    int n = blockIdx.x * blockDim.x + threadIdx.x;
    if (n < N_NODES) {
        float d = g_deg[n];
        g_deg[n] = 1.0f / fmaxf(d, 1.0f);
    }
}

// ---------------- layer-0 aggregation (6-dim) ----------------
__global__ void k_agg0(const int* __restrict__ ei, const float* __restrict__ x) {
    int e = blockIdx.x * blockDim.x + threadIdx.x;
    if (e >= N_EDGES) return;
    int s = ei[e];
    int d = ei[N_EDGES + e];
    const float* xs = x + s * IN_DIM;
    float* a = g_agg0 + d * IN_DIM;
#pragma unroll
    for (int k = 0; k < IN_DIM; k++) atomicAdd(&a[k], xs[k]);
}

// ---------------- layer-0 conv: h0 = mean_nb @ wl.T + bl + x @ wr.T ----------------
// block = 128 threads (one per output channel), 32 nodes per block
__global__ void k_layer0(const float* __restrict__ x,
                         const float* __restrict__ wl, const float* __restrict__ bl,
                         const float* __restrict__ wr) {
    __shared__ float sIn[32 * 12];   // per node: [mean6 | x6]
    int n0 = blockIdx.x * 32;
    int tid = threadIdx.x;

    float wlr[IN_DIM], wrr[IN_DIM];
#pragma unroll
    for (int k = 0; k < IN_DIM; k++) {
        wlr[k] = __ldg(&wl[tid * IN_DIM + k]);
        wrr[k] = __ldg(&wr[tid * IN_DIM + k]);
    }
    float bias = __ldg(&bl[tid]);

#pragma unroll
    for (int it = 0; it < 3; it++) {
        int i = tid + it * 128;          // 0..383
        int n = n0 + i / 12, f = i % 12;
        float v = 0.0f;
        if (n < N_NODES) {
            if (f < 6) v = g_agg0[n * IN_DIM + f] * g_deg[n];
            else       v = x[n * IN_DIM + (f - 6)];
        }
        sIn[i] = v;
    }
    __syncthreads();

    for (int i = 0; i < 32; i++) {
        int n = n0 + i;
        if (n >= N_NODES) break;
        const float* in = &sIn[i * 12];
        float h = bias;
#pragma unroll
        for (int k = 0; k < IN_DIM; k++) h += wlr[k] * in[k] + wrr[k] * in[6 + k];
        g_h0[n * HID + tid] = h;
    }
}

// ---------------- BN stats (block-partial sums -> 1 atomic per block/channel) ----------------
__device__ __forceinline__ void bnstats_body(const float* h) {
    int c = threadIdx.x;
    int n0 = blockIdx.x * 64;
    float s = 0.0f, s2 = 0.0f;
    for (int i = 0; i < 64; i++) {
        int n = n0 + i;
        if (n >= N_NODES) break;
        float v = h[n * HID + c];
        s += v; s2 += v * v;
    }
    atomicAdd(&g_sum[c], s);
    atomicAdd(&g_sq[c], s2);
}
__global__ void k_bnstats0() { bnstats_body(g_h0); }
__global__ void k_bnstats1() { bnstats_body(g_h1); }

__global__ void k_bnfinal(const float* __restrict__ gamma, const float* __restrict__ beta) {
    int c = threadIdx.x;
    float mu  = g_sum[c] * (1.0f / N_NODES);
    float var = g_sq[c] * (1.0f / N_NODES) - mu * mu;
    float sc  = gamma[c] * rsqrtf(var + EPS);
    g_scale[c] = sc;
    g_shift[c] = beta[c] - mu * sc;
}

// elementwise BN + ReLU in place, float4 (channels are inner dim, 128 = 32 float4)
__device__ __forceinline__ void bnrelu_body(float* h) {
    int i = blockIdx.x * blockDim.x + threadIdx.x;   // 3.2M float4
    if (i >= N_NODES * (HID / 4)) return;
    int c4 = (i & 31) * 4;
    float4 v = ((float4*)h)[i];
    float4 sc = *(const float4*)&g_scale[c4];
    float4 sh = *(const float4*)&g_shift[c4];
    v.x = fmaxf(fmaf(v.x, sc.x, sh.x), 0.0f);
    v.y = fmaxf(fmaf(v.y, sc.y, sh.y), 0.0f);
    v.z = fmaxf(fmaf(v.z, sc.z, sh.z), 0.0f);
    v.w = fmaxf(fmaf(v.w, sc.w, sh.w), 0.0f);
    ((float4*)h)[i] = v;
}
__global__ void k_bnrelu0() { bnrelu_body(g_h0); }
__global__ void k_bnrelu1() { bnrelu_body(g_h1); }

// ---------------- layer-1 aggregation: 32 lanes per edge, float4 per lane ----------------
__global__ void k_agg1(const int* __restrict__ ei) {
    int gt = blockIdx.x * blockDim.x + threadIdx.x;
    int e = gt >> 5;
    if (e >= N_EDGES) return;
    int lane = threadIdx.x & 31;
    int s = __ldg(&ei[e]);
    int d = __ldg(&ei[N_EDGES + e]);
    float4 v = ((const float4*)(g_h0 + s * HID))[lane];
    float* a = g_agg1 + d * HID + lane * 4;
    atomicAdd(a + 0, v.x);
    atomicAdd(a + 1, v.y);
    atomicAdd(a + 2, v.z);
    atomicAdd(a + 3, v.w);
}

// ---------------- layer-1 fused GEMM: h1 = (agg1*inv) @ wl.T + bl + h0 @ wr.T ----------------
// BM=64 nodes, BN=128 channels (full), BK=16. 256 threads, each computes 8 nodes x 4 channels.
__global__ void __launch_bounds__(256) k_gemm1(const float* __restrict__ wl,
                                               const float* __restrict__ bl,
                                               const float* __restrict__ wr) {
    __shared__ float As[16][64];
    __shared__ float Ws[16][128];
    __shared__ float sInv[64];

    int tid = threadIdx.x;
    int n0 = blockIdx.x * 64;

    if (tid < 64) {
        int n = n0 + tid;
        sInv[tid] = (n < N_NODES) ? g_deg[n] : 0.0f;
    }

    int rn = (tid & 7) * 8;     // node sub-tile 0..56
    int rc = (tid >> 3) * 4;    // channel sub-tile 0..124

    float acc[8][4];
#pragma unroll
    for (int i = 0; i < 8; i++)
#pragma unroll
        for (int j = 0; j < 4; j++) acc[i][j] = 0.0f;

    __syncthreads();

#pragma unroll 1
    for (int p = 0; p < 2; p++) {
        const float* A = p ? g_h0 : g_agg1;
        const float* W = p ? wr : wl;
#pragma unroll 1
        for (int kt = 0; kt < HID; kt += 16) {
            __syncthreads();
            // A tile: 64x16, transposed into As[k][n]
            {
                int nA = tid >> 2;
                int jA = (tid & 3) * 4;
                int n = n0 + nA;
                float4 v = make_float4(0.f, 0.f, 0.f, 0.f);
                if (n < N_NODES) v = *(const float4*)(A + n * HID + kt + jA);
                if (p == 0) {
                    float iv = sInv[nA];
                    v.x *= iv; v.y *= iv; v.z *= iv; v.w *= iv;
                }
                As[jA + 0][nA] = v.x;
                As[jA + 1][nA] = v.y;
                As[jA + 2][nA] = v.z;
                As[jA + 3][nA] = v.w;
            }
            // W tile: 128x16, transposed into Ws[k][c]
            {
                int c = tid >> 1;
                int jW = (tid & 1) * 8;
                const float4* wp = (const float4*)(W + c * HID + kt + jW);
                float4 w0 = __ldg(wp);
                float4 w1 = __ldg(wp + 1);
                Ws[jW + 0][c] = w0.x; Ws[jW + 1][c] = w0.y;
                Ws[jW + 2][c] = w0.z; Ws[jW + 3][c] = w0.w;
                Ws[jW + 4][c] = w1.x; Ws[jW + 5][c] = w1.y;
                Ws[jW + 6][c] = w1.z; Ws[jW + 7][c] = w1.w;
            }
            __syncthreads();
#pragma unroll
            for (int j = 0; j < 16; j++) {
                float4 w = *(float4*)&Ws[j][rc];
                float4 a0 = *(float4*)&As[j][rn];
                float4 a1 = *(float4*)&As[j][rn + 4];
                float av[8] = {a0.x, a0.y, a0.z, a0.w, a1.x, a1.y, a1.z, a1.w};
#pragma unroll
                for (int i = 0; i < 8; i++) {
                    acc[i][0] = fmaf(av[i], w.x, acc[i][0]);
                    acc[i][1] = fmaf(av[i], w.y, acc[i][1]);
                    acc[i][2] = fmaf(av[i], w.z, acc[i][2]);
                    acc[i][3] = fmaf(av[i], w.w, acc[i][3]);
                }
            }
        }
    }

    float4 bias = __ldg((const float4*)(bl + rc));
#pragma unroll
    for (int i = 0; i < 8; i++) {
        int n = n0 + rn + i;
        if (n < N_NODES) {
            float4 o;
            o.x = acc[i][0] + bias.x;
            o.y = acc[i][1] + bias.y;
            o.z = acc[i][2] + bias.z;
            o.w = acc[i][3] + bias.w;
            *(float4*)(g_h1 + n * HID + rc) = o;
        }
    }
}

// ---------------- layer-2: project to scalar first (linearity), then aggregate scalars ----------------
__global__ void k_proj2(const float* __restrict__ wl2, const float* __restrict__ wr2) {
    int gt = blockIdx.x * blockDim.x + threadIdx.x;
    int n = gt >> 5;
    if (n >= N_NODES) return;
    int lane = threadIdx.x & 31;
    float4 h = ((const float4*)(g_h1 + n * HID))[lane];
    float4 a = __ldg((const float4*)wl2 + lane);
    float4 b = __ldg((const float4*)wr2 + lane);
    float pl = h.x * a.x + h.y * a.y + h.z * a.z + h.w * a.w;
    float pr = h.x * b.x + h.y * b.y + h.z * b.z + h.w * b.w;
#pragma unroll
    for (int o = 16; o > 0; o >>= 1) {
        pl += __shfl_xor_sync(0xffffffffu, pl, o);
        pr += __shfl_xor_sync(0xffffffffu, pr, o);
    }
    if (lane == 0) { g_pl[n] = pl; g_pr[n] = pr; }
}

__global__ void k_agg2(const int* __restrict__ ei) {
    int e = blockIdx.x * blockDim.x + threadIdx.x;
    if (e >= N_EDGES) return;
    int s = ei[e];
    int d = ei[N_EDGES + e];
    atomicAdd(&g_acc2[d], g_pl[s]);
}

__global__ void k_final(const float* __restrict__ bl2, float* __restrict__ out) {
    int n = blockIdx.x * blockDim.x + threadIdx.x;
    if (n < N_NODES) {
        float z = g_acc2[n] * g_deg[n] + __ldg(bl2) + g_pr[n];
        out[n] = 1.0f / (1.0f + expf(-z));
    }
}

// ---------------- launch: kernel launches ONLY, no other CUDA API ----------------
extern "C" void kernel_launch(void* const* d_in, const int* in_sizes, int n_in,
                              void* d_out, int out_size) {
    const float* x   = (const float*)d_in[0];
    const int*   ei  = (const int*)d_in[1];   // int32! (JAX demotes int64)
    const float* wl0 = (const float*)d_in[2];
    const float* bl0 = (const float*)d_in[3];
    const float* wr0 = (const float*)d_in[4];
    const float* g0  = (const float*)d_in[5];
    const float* b0  = (const float*)d_in[6];
    const float* wl1 = (const float*)d_in[7];
    const float* bl1 = (const float*)d_in[8];
    const float* wr1 = (const float*)d_in[9];
    const float* g1  = (const float*)d_in[10];
    const float* b1  = (const float*)d_in[11];
    const float* wl2 = (const float*)d_in[12];
    const float* bl2 = (const float*)d_in[13];
    const float* wr2 = (const float*)d_in[14];
    float* out = (float*)d_out;

    k_zero_big<<<2048, 256>>>();

    k_deg   <<<(N_EDGES + 255) / 256, 256>>>(ei);
    k_agg0  <<<(N_EDGES + 255) / 256, 256>>>(ei, x);
    k_invdeg<<<(N_NODES + 255) / 256, 256>>>();
    k_layer0<<<(N_NODES + 31) / 32, 128>>>(x, wl0, bl0, wr0);

    k_bnstats0<<<(N_NODES + 63) / 64, 128>>>();
    k_bnfinal <<<1, 128>>>(g0, b0);
    k_bnrelu0 <<<(N_NODES * (HID / 4) + 255) / 256, 256>>>();

    k_agg1 <<<(N_EDGES * 32 + 255) / 256, 256>>>(ei);
    k_gemm1<<<(N_NODES + 63) / 64, 256>>>(wl1, bl1, wr1);

    k_zero_bn <<<1, 128>>>();
    k_bnstats1<<<(N_NODES + 63) / 64, 128>>>();
    k_bnfinal <<<1, 128>>>(g1, b1);
    k_bnrelu1 <<<(N_NODES * (HID / 4) + 255) / 256, 256>>>();

    k_proj2<<<(N_NODES * 32 + 255) / 256, 256>>>(wl2, wr2);
    k_agg2 <<<(N_EDGES + 255) / 256, 256>>>(ei);
    k_final<<<(N_NODES + 255) / 256, 256>>>(bl2, out);
}

// round 7
// speedup vs baseline: 2.0363x; 2.0363x over previous
#include <cuda_runtime.h>

#define N_NODES 100000
#define N_EDGES 600000
#define IN_DIM  6
#define HID     128
#define EPS     1e-5f
#define SCAN_B  1024
#define SCAN_NB ((N_NODES + SCAN_B - 1) / SCAN_B)   // 98

// ---------------- scratch (device globals: allocation-free) ----------------
__device__ __align__(16) int   g_degi[N_NODES];           // int degree counts
__device__ __align__(16) int   g_off[N_NODES + 1];        // CSR offsets (exclusive)
__device__ __align__(16) int   g_cur[N_NODES];            // scatter cursors
__device__ __align__(16) int   g_esrc[N_EDGES];           // src ids grouped by dst
__device__ __align__(16) int   g_bsum[SCAN_NB];           // scan block sums
__device__ __align__(16) float g_inv[N_NODES];            // 1/max(deg,1)
__device__ __align__(16) float g_agg0[N_NODES * IN_DIM];  // layer-0 neighbor MEAN (6-dim)
__device__ __align__(16) float g_h0[N_NODES * HID];       // layer-0 out -> BN+ReLU in place
__device__ __align__(16) float g_agg1[N_NODES * HID];     // layer-1 neighbor MEAN
__device__ __align__(16) float g_h1[N_NODES * HID];       // layer-1 out -> BN+ReLU in place
__device__ __align__(16) float g_sum[HID];                // BN partial sums
__device__ __align__(16) float g_sq[HID];
__device__ __align__(16) float g_scale[HID];              // BN affine
__device__ __align__(16) float g_shift[HID];
__device__ __align__(16) float g_pl[N_NODES];             // layer-2 projections
__device__ __align__(16) float g_pr[N_NODES];

// ---------------- zeroing (kernels only) ----------------
__global__ void k_zero() {
    int i = blockIdx.x * blockDim.x + threadIdx.x;
    int stride = gridDim.x * blockDim.x;
    for (int j = i; j < N_NODES; j += stride) { g_degi[j] = 0; g_cur[j] = 0; }
    if (i < HID) { g_sum[i] = 0.0f; g_sq[i] = 0.0f; }
}

__global__ void k_zero_bn() {
    g_sum[threadIdx.x] = 0.0f;
    g_sq[threadIdx.x] = 0.0f;
}

// ---------------- CSR build ----------------
__global__ void k_count(const int* __restrict__ ei) {
    int e = blockIdx.x * blockDim.x + threadIdx.x;
    if (e < N_EDGES) atomicAdd(&g_degi[ei[N_EDGES + e]], 1);
}

__global__ void k_scan1() {
    __shared__ int s[SCAN_B];
    int tid = threadIdx.x;
    int i = blockIdx.x * SCAN_B + tid;
    int v = (i < N_NODES) ? g_degi[i] : 0;
    s[tid] = v;
    __syncthreads();
#pragma unroll
    for (int o = 1; o < SCAN_B; o <<= 1) {
        int t = (tid >= o) ? s[tid - o] : 0;
        __syncthreads();
        s[tid] += t;
        __syncthreads();
    }
    if (i < N_NODES) g_off[i + 1] = s[tid];
    if (tid == SCAN_B - 1) g_bsum[blockIdx.x] = s[tid];
}

__global__ void k_scan2() {
    if (threadIdx.x == 0) {
        int run = 0;
        for (int b = 0; b < SCAN_NB; b++) { int t = g_bsum[b]; g_bsum[b] = run; run += t; }
    }
}

__global__ void k_scan3() {
    int i = blockIdx.x * SCAN_B + threadIdx.x;
    if (i < N_NODES) g_off[i + 1] += g_bsum[blockIdx.x];
    if (i == 0) g_off[0] = 0;
}

__global__ void k_fill(const int* __restrict__ ei) {
    int e = blockIdx.x * blockDim.x + threadIdx.x;
    if (e >= N_EDGES) return;
    int s = ei[e];
    int d = ei[N_EDGES + e];
    int pos = g_off[d] + atomicAdd(&g_cur[d], 1);
    g_esrc[pos] = s;
}

__global__ void k_inv() {
    int n = blockIdx.x * blockDim.x + threadIdx.x;
    if (n < N_NODES) g_inv[n] = 1.0f / fmaxf((float)g_degi[n], 1.0f);
}

// ---------------- layer-0 aggregation (mean, 6-dim, CSR) ----------------
__global__ void k_agg0(const float* __restrict__ x) {
    int n = blockIdx.x * blockDim.x + threadIdx.x;
    if (n >= N_NODES) return;
    int beg = g_off[n], end = g_off[n + 1];
    float a[IN_DIM] = {0.f, 0.f, 0.f, 0.f, 0.f, 0.f};
    for (int j = beg; j < end; j++) {
        int s = g_esrc[j];
        const float* xs = x + s * IN_DIM;
#pragma unroll
        for (int k = 0; k < IN_DIM; k++) a[k] += xs[k];
    }
    float iv = g_inv[n];
#pragma unroll
    for (int k = 0; k < IN_DIM; k++) g_agg0[n * IN_DIM + k] = a[k] * iv;
}

// ---------------- layer-0 conv: h0 = mean0 @ wl.T + bl + x @ wr.T ----------------
__global__ void k_layer0(const float* __restrict__ x,
                         const float* __restrict__ wl, const float* __restrict__ bl,
                         const float* __restrict__ wr) {
    __shared__ float sIn[32 * 12];   // per node: [mean6 | x6]
    int n0 = blockIdx.x * 32;
    int tid = threadIdx.x;

    float wlr[IN_DIM], wrr[IN_DIM];
#pragma unroll
    for (int k = 0; k < IN_DIM; k++) {
        wlr[k] = __ldg(&wl[tid * IN_DIM + k]);
        wrr[k] = __ldg(&wr[tid * IN_DIM + k]);
    }
    float bias = __ldg(&bl[tid]);

#pragma unroll
    for (int it = 0; it < 3; it++) {
        int i = tid + it * 128;          // 0..383
        int n = n0 + i / 12, f = i % 12;
        float v = 0.0f;
        if (n < N_NODES) {
            if (f < 6) v = g_agg0[n * IN_DIM + f];
            else       v = x[n * IN_DIM + (f - 6)];
        }
        sIn[i] = v;
    }
    __syncthreads();

    for (int i = 0; i < 32; i++) {
        int n = n0 + i;
        if (n >= N_NODES) break;
        const float* in = &sIn[i * 12];
        float h = bias;
#pragma unroll
        for (int k = 0; k < IN_DIM; k++) h += wlr[k] * in[k] + wrr[k] * in[6 + k];
        g_h0[n * HID + tid] = h;
    }
}

// ---------------- BN stats ----------------
__device__ __forceinline__ void bnstats_body(const float* h) {
    int c = threadIdx.x;
    int n0 = blockIdx.x * 64;
    float s = 0.0f, s2 = 0.0f;
    for (int i = 0; i < 64; i++) {
        int n = n0 + i;
        if (n >= N_NODES) break;
        float v = h[n * HID + c];
        s += v; s2 += v * v;
    }
    atomicAdd(&g_sum[c], s);
    atomicAdd(&g_sq[c], s2);
}
__global__ void k_bnstats0() { bnstats_body(g_h0); }
__global__ void k_bnstats1() { bnstats_body(g_h1); }

__global__ void k_bnfinal(const float* __restrict__ gamma, const float* __restrict__ beta) {
    int c = threadIdx.x;
    float mu  = g_sum[c] * (1.0f / N_NODES);
    float var = g_sq[c] * (1.0f / N_NODES) - mu * mu;
    float sc  = gamma[c] * rsqrtf(var + EPS);
    g_scale[c] = sc;
    g_shift[c] = beta[c] - mu * sc;
}

__device__ __forceinline__ void bnrelu_body(float* h) {
    int i = blockIdx.x * blockDim.x + threadIdx.x;
    if (i >= N_NODES * (HID / 4)) return;
    int c4 = (i & 31) * 4;
    float4 v = ((float4*)h)[i];
    float4 sc = *(const float4*)&g_scale[c4];
    float4 sh = *(const float4*)&g_shift[c4];
    v.x = fmaxf(fmaf(v.x, sc.x, sh.x), 0.0f);
    v.y = fmaxf(fmaf(v.y, sc.y, sh.y), 0.0f);
    v.z = fmaxf(fmaf(v.z, sc.z, sh.z), 0.0f);
    v.w = fmaxf(fmaf(v.w, sc.w, sh.w), 0.0f);
    ((float4*)h)[i] = v;
}
__global__ void k_bnrelu0() { bnrelu_body(g_h0); }
__global__ void k_bnrelu1() { bnrelu_body(g_h1); }

// ---------------- layer-1 aggregation (mean, CSR): one warp per node ----------------
__global__ void k_agg1() {
    int w = (blockIdx.x * blockDim.x + threadIdx.x) >> 5;
    if (w >= N_NODES) return;
    int lane = threadIdx.x & 31;
    int beg = __ldg(&g_off[w]), end = __ldg(&g_off[w + 1]);
    float4 acc = make_float4(0.f, 0.f, 0.f, 0.f);
    for (int j = beg; j < end; j++) {
        int s = __ldg(&g_esrc[j]);                 // broadcast load
        float4 v = ((const float4*)(g_h0 + s * HID))[lane];
        acc.x += v.x; acc.y += v.y; acc.z += v.z; acc.w += v.w;
    }
    float iv = g_inv[w];
    acc.x *= iv; acc.y *= iv; acc.z *= iv; acc.w *= iv;
    ((float4*)(g_agg1 + w * HID))[lane] = acc;
}

// ---------------- layer-1 fused GEMM: h1 = mean1 @ wl.T + bl + h0 @ wr.T ----------------
__global__ void __launch_bounds__(256) k_gemm1(const float* __restrict__ wl,
                                               const float* __restrict__ bl,
                                               const float* __restrict__ wr) {
    __shared__ float As[16][64];
    __shared__ float Ws[16][128];

    int tid = threadIdx.x;
    int n0 = blockIdx.x * 64;

    int rn = (tid & 7) * 8;     // node sub-tile 0..56
    int rc = (tid >> 3) * 4;    // channel sub-tile 0..124

    float acc[8][4];
#pragma unroll
    for (int i = 0; i < 8; i++)
#pragma unroll
        for (int j = 0; j < 4; j++) acc[i][j] = 0.0f;

#pragma unroll 1
    for (int p = 0; p < 2; p++) {
        const float* A = p ? g_h0 : g_agg1;
        const float* W = p ? wr : wl;
#pragma unroll 1
        for (int kt = 0; kt < HID; kt += 16) {
            __syncthreads();
            {
                int nA = tid >> 2;
                int jA = (tid & 3) * 4;
                int n = n0 + nA;
                float4 v = make_float4(0.f, 0.f, 0.f, 0.f);
                if (n < N_NODES) v = *(const float4*)(A + n * HID + kt + jA);
                As[jA + 0][nA] = v.x;
                As[jA + 1][nA] = v.y;
                As[jA + 2][nA] = v.z;
                As[jA + 3][nA] = v.w;
            }
            {
                int c = tid >> 1;
                int jW = (tid & 1) * 8;
                const float4* wp = (const float4*)(W + c * HID + kt + jW);
                float4 w0 = __ldg(wp);
                float4 w1 = __ldg(wp + 1);
                Ws[jW + 0][c] = w0.x; Ws[jW + 1][c] = w0.y;
                Ws[jW + 2][c] = w0.z; Ws[jW + 3][c] = w0.w;
                Ws[jW + 4][c] = w1.x; Ws[jW + 5][c] = w1.y;
                Ws[jW + 6][c] = w1.z; Ws[jW + 7][c] = w1.w;
            }
            __syncthreads();
#pragma unroll
            for (int j = 0; j < 16; j++) {
                float4 w = *(float4*)&Ws[j][rc];
                float4 a0 = *(float4*)&As[j][rn];
                float4 a1 = *(float4*)&As[j][rn + 4];
                float av[8] = {a0.x, a0.y, a0.z, a0.w, a1.x, a1.y, a1.z, a1.w};
#pragma unroll
                for (int i = 0; i < 8; i++) {
                    acc[i][0] = fmaf(av[i], w.x, acc[i][0]);
                    acc[i][1] = fmaf(av[i], w.y, acc[i][1]);
                    acc[i][2] = fmaf(av[i], w.z, acc[i][2]);
                    acc[i][3] = fmaf(av[i], w.w, acc[i][3]);
                }
            }
        }
    }

    float4 bias = __ldg((const float4*)(bl + rc));
#pragma unroll
    for (int i = 0; i < 8; i++) {
        int n = n0 + rn + i;
        if (n < N_NODES) {
            float4 o;
            o.x = acc[i][0] + bias.x;
            o.y = acc[i][1] + bias.y;
            o.z = acc[i][2] + bias.z;
            o.w = acc[i][3] + bias.w;
            *(float4*)(g_h1 + n * HID + rc) = o;
        }
    }
}

// ---------------- layer-2: project to scalars, then CSR-aggregate + sigmoid ----------------
__global__ void k_proj2(const float* __restrict__ wl2, const float* __restrict__ wr2) {
    int gt = blockIdx.x * blockDim.x + threadIdx.x;
    int n = gt >> 5;
    if (n >= N_NODES) return;
    int lane = threadIdx.x & 31;
    float4 h = ((const float4*)(g_h1 + n * HID))[lane];
    float4 a = __ldg((const float4*)wl2 + lane);
    float4 b = __ldg((const float4*)wr2 + lane);
    float pl = h.x * a.x + h.y * a.y + h.z * a.z + h.w * a.w;
    float pr = h.x * b.x + h.y * b.y + h.z * b.z + h.w * b.w;
#pragma unroll
    for (int o = 16; o > 0; o >>= 1) {
        pl += __shfl_xor_sync(0xffffffffu, pl, o);
        pr += __shfl_xor_sync(0xffffffffu, pr, o);
    }
    if (lane == 0) { g_pl[n] = pl; g_pr[n] = pr; }
}

__global__ void k_final(const float* __restrict__ bl2, float* __restrict__ out) {
    int n = blockIdx.x * blockDim.x + threadIdx.x;
    if (n >= N_NODES) return;
    int beg = g_off[n], end = g_off[n + 1];
    float a = 0.0f;
    for (int j = beg; j < end; j++) a += g_pl[g_esrc[j]];
    float z = a * g_inv[n] + __ldg(bl2) + g_pr[n];
    out[n] = 1.0f / (1.0f + expf(-z));
}

// ---------------- launch: kernel launches ONLY ----------------
extern "C" void kernel_launch(void* const* d_in, const int* in_sizes, int n_in,
                              void* d_out, int out_size) {
    const float* x   = (const float*)d_in[0];
    const int*   ei  = (const int*)d_in[1];   // int32 (JAX x64-disabled demotes int64)
    const float* wl0 = (const float*)d_in[2];
    const float* bl0 = (const float*)d_in[3];
    const float* wr0 = (const float*)d_in[4];
    const float* g0  = (const float*)d_in[5];
    const float* b0  = (const float*)d_in[6];
    const float* wl1 = (const float*)d_in[7];
    const float* bl1 = (const float*)d_in[8];
    const float* wr1 = (const float*)d_in[9];
    const float* g1  = (const float*)d_in[10];
    const float* b1  = (const float*)d_in[11];
    const float* wl2 = (const float*)d_in[12];
    const float* bl2 = (const float*)d_in[13];
    const float* wr2 = (const float*)d_in[14];
    float* out = (float*)d_out;

    k_zero <<<512, 256>>>();

    // CSR build
    k_count<<<(N_EDGES + 255) / 256, 256>>>(ei);
    k_scan1<<<SCAN_NB, SCAN_B>>>();
    k_scan2<<<1, 32>>>();
    k_scan3<<<SCAN_NB, SCAN_B>>>();
    k_fill <<<(N_EDGES + 255) / 256, 256>>>(ei);
    k_inv  <<<(N_NODES + 255) / 256, 256>>>();

    // layer 0
    k_agg0  <<<(N_NODES + 255) / 256, 256>>>(x);
    k_layer0<<<(N_NODES + 31) / 32, 128>>>(x, wl0, bl0, wr0);
    k_bnstats0<<<(N_NODES + 63) / 64, 128>>>();
    k_bnfinal <<<1, 128>>>(g0, b0);
    k_bnrelu0 <<<(N_NODES * (HID / 4) + 255) / 256, 256>>>();

    // layer 1
    k_agg1 <<<(N_NODES * 32 + 255) / 256, 256>>>();
    k_gemm1<<<(N_NODES + 63) / 64, 256>>>(wl1, bl1, wr1);
    k_zero_bn <<<1, 128>>>();
    k_bnstats1<<<(N_NODES + 63) / 64, 128>>>();
    k_bnfinal <<<1, 128>>>(g1, b1);
    k_bnrelu1 <<<(N_NODES * (HID / 4) + 255) / 256, 256>>>();

    // layer 2
    k_proj2<<<(N_NODES * 32 + 255) / 256, 256>>>(wl2, wr2);
    k_final<<<(N_NODES + 255) / 256, 256>>>(bl2, out);
}

// round 9
// speedup vs baseline: 3.6738x; 1.8041x over previous
#include <cuda_runtime.h>
#include <cstdint>

#define N_NODES 100000
#define N_EDGES 600000
#define IN_DIM  6
#define HID     128
#define EPS     1e-5f
#define SCAN_B  1024
#define SCAN_NB ((N_NODES + SCAN_B - 1) / SCAN_B)   // 98

// ---------------- scratch (device globals: allocation-free) ----------------
__device__ __align__(16) int   g_degi[N_NODES];           // int degree counts
__device__ __align__(16) int   g_off[N_NODES + 1];        // CSR offsets (exclusive)
__device__ __align__(16) int   g_cur[N_NODES];            // scatter cursors
__device__ __align__(16) int   g_esrc[N_EDGES];           // src ids grouped by dst
__device__ __align__(16) int   g_bsum[SCAN_NB];           // scan block sums
__device__ __align__(16) float g_inv[N_NODES];            // 1/max(deg,1)
__device__ __align__(16) float g_agg0[N_NODES * IN_DIM];  // layer-0 neighbor MEAN (6-dim)
__device__ __align__(16) float g_h0[N_NODES * HID];       // layer-0 out -> BN+ReLU in place
__device__ __align__(16) float g_agg1[N_NODES * HID];     // layer-1 neighbor MEAN
__device__ __align__(16) float g_h1[N_NODES * HID];       // layer-1 out -> BN+ReLU in place
__device__ __align__(16) float g_sum[HID];                // BN partial sums
__device__ __align__(16) float g_sq[HID];
__device__ __align__(16) float g_scale[HID];              // BN affine
__device__ __align__(16) float g_shift[HID];
__device__ __align__(16) float g_pl[N_NODES];             // layer-2 projections
__device__ __align__(16) float g_pr[N_NODES];

// ---------------- zeroing (kernels only) ----------------
__global__ void k_zero() {
    int i = blockIdx.x * blockDim.x + threadIdx.x;
    int stride = gridDim.x * blockDim.x;
    for (int j = i; j < N_NODES; j += stride) { g_degi[j] = 0; g_cur[j] = 0; }
    if (i < HID) { g_sum[i] = 0.0f; g_sq[i] = 0.0f; }
}

__global__ void k_zero_bn() {
    g_sum[threadIdx.x] = 0.0f;
    g_sq[threadIdx.x] = 0.0f;
}

// ---------------- CSR build ----------------
__global__ void k_count(const int* __restrict__ ei) {
    int e = blockIdx.x * blockDim.x + threadIdx.x;
    if (e < N_EDGES) atomicAdd(&g_degi[ei[N_EDGES + e]], 1);
}

__global__ void k_scan1() {
    __shared__ int s[SCAN_B];
    int tid = threadIdx.x;
    int i = blockIdx.x * SCAN_B + tid;
    int v = (i < N_NODES) ? g_degi[i] : 0;
    s[tid] = v;
    __syncthreads();
#pragma unroll
    for (int o = 1; o < SCAN_B; o <<= 1) {
        int t = (tid >= o) ? s[tid - o] : 0;
        __syncthreads();
        s[tid] += t;
        __syncthreads();
    }
    if (i < N_NODES) g_off[i + 1] = s[tid];
    if (tid == SCAN_B - 1) g_bsum[blockIdx.x] = s[tid];
}

__global__ void k_scan2() {
    if (threadIdx.x == 0) {
        int run = 0;
        for (int b = 0; b < SCAN_NB; b++) { int t = g_bsum[b]; g_bsum[b] = run; run += t; }
    }
}

__global__ void k_scan3() {
    int i = blockIdx.x * SCAN_B + threadIdx.x;
    if (i < N_NODES) g_off[i + 1] += g_bsum[blockIdx.x];
    if (i == 0) g_off[0] = 0;
}

__global__ void k_fill(const int* __restrict__ ei) {
    int e = blockIdx.x * blockDim.x + threadIdx.x;
    if (e >= N_EDGES) return;
    int s = ei[e];
    int d = ei[N_EDGES + e];
    int pos = g_off[d] + atomicAdd(&g_cur[d], 1);
    g_esrc[pos] = s;
}

__global__ void k_inv() {
    int n = blockIdx.x * blockDim.x + threadIdx.x;
    if (n < N_NODES) g_inv[n] = 1.0f / fmaxf((float)g_degi[n], 1.0f);
}

// ---------------- layer-0 aggregation (mean, 6-dim, CSR) ----------------
__global__ void k_agg0(const float* __restrict__ x) {
    int n = blockIdx.x * blockDim.x + threadIdx.x;
    if (n >= N_NODES) return;
    int beg = g_off[n], end = g_off[n + 1];
    float a[IN_DIM] = {0.f, 0.f, 0.f, 0.f, 0.f, 0.f};
    for (int j = beg; j < end; j++) {
        int s = g_esrc[j];
        const float* xs = x + s * IN_DIM;
#pragma unroll
        for (int k = 0; k < IN_DIM; k++) a[k] += xs[k];
    }
    float iv = g_inv[n];
#pragma unroll
    for (int k = 0; k < IN_DIM; k++) g_agg0[n * IN_DIM + k] = a[k] * iv;
}

// ---------------- layer-0 conv: h0 = mean0 @ wl.T + bl + x @ wr.T ----------------
__global__ void k_layer0(const float* __restrict__ x,
                         const float* __restrict__ wl, const float* __restrict__ bl,
                         const float* __restrict__ wr) {
    __shared__ float sIn[32 * 12];   // per node: [mean6 | x6]
    int n0 = blockIdx.x * 32;
    int tid = threadIdx.x;

    float wlr[IN_DIM], wrr[IN_DIM];
#pragma unroll
    for (int k = 0; k < IN_DIM; k++) {
        wlr[k] = __ldg(&wl[tid * IN_DIM + k]);
        wrr[k] = __ldg(&wr[tid * IN_DIM + k]);
    }
    float bias = __ldg(&bl[tid]);

#pragma unroll
    for (int it = 0; it < 3; it++) {
        int i = tid + it * 128;          // 0..383
        int n = n0 + i / 12, f = i % 12;
        float v = 0.0f;
        if (n < N_NODES) {
            if (f < 6) v = g_agg0[n * IN_DIM + f];
            else       v = x[n * IN_DIM + (f - 6)];
        }
        sIn[i] = v;
    }
    __syncthreads();

    for (int i = 0; i < 32; i++) {
        int n = n0 + i;
        if (n >= N_NODES) break;
        const float* in = &sIn[i * 12];
        float h = bias;
#pragma unroll
        for (int k = 0; k < IN_DIM; k++) h += wlr[k] * in[k] + wrr[k] * in[6 + k];
        g_h0[n * HID + tid] = h;
    }
}

// ---------------- BN stats ----------------
__device__ __forceinline__ void bnstats_body(const float* h) {
    int c = threadIdx.x;
    int n0 = blockIdx.x * 64;
    float s = 0.0f, s2 = 0.0f;
    for (int i = 0; i < 64; i++) {
        int n = n0 + i;
        if (n >= N_NODES) break;
        float v = h[n * HID + c];
        s += v; s2 += v * v;
    }
    atomicAdd(&g_sum[c], s);
    atomicAdd(&g_sq[c], s2);
}
__global__ void k_bnstats0() { bnstats_body(g_h0); }
__global__ void k_bnstats1() { bnstats_body(g_h1); }

__global__ void k_bnfinal(const float* __restrict__ gamma, const float* __restrict__ beta) {
    int c = threadIdx.x;
    float mu  = g_sum[c] * (1.0f / N_NODES);
    float var = g_sq[c] * (1.0f / N_NODES) - mu * mu;
    float sc  = gamma[c] * rsqrtf(var + EPS);
    g_scale[c] = sc;
    g_shift[c] = beta[c] - mu * sc;
}

__device__ __forceinline__ void bnrelu_body(float* h) {
    int i = blockIdx.x * blockDim.x + threadIdx.x;
    if (i >= N_NODES * (HID / 4)) return;
    int c4 = (i & 31) * 4;
    float4 v = ((float4*)h)[i];
    float4 sc = *(const float4*)&g_scale[c4];
    float4 sh = *(const float4*)&g_shift[c4];
    v.x = fmaxf(fmaf(v.x, sc.x, sh.x), 0.0f);
    v.y = fmaxf(fmaf(v.y, sc.y, sh.y), 0.0f);
    v.z = fmaxf(fmaf(v.z, sc.z, sh.z), 0.0f);
    v.w = fmaxf(fmaf(v.w, sc.w, sh.w), 0.0f);
    ((float4*)h)[i] = v;
}
__global__ void k_bnrelu0() { bnrelu_body(g_h0); }
__global__ void k_bnrelu1() { bnrelu_body(g_h1); }

// ---------------- layer-1 aggregation (mean, CSR): one warp per node ----------------
__global__ void k_agg1() {
    int w = (blockIdx.x * blockDim.x + threadIdx.x) >> 5;
    if (w >= N_NODES) return;
    int lane = threadIdx.x & 31;
    int beg = __ldg(&g_off[w]), end = __ldg(&g_off[w + 1]);
    float4 acc = make_float4(0.f, 0.f, 0.f, 0.f);
    for (int j = beg; j < end; j++) {
        int s = __ldg(&g_esrc[j]);                 // broadcast load
        float4 v = ((const float4*)(g_h0 + s * HID))[lane];
        acc.x += v.x; acc.y += v.y; acc.z += v.z; acc.w += v.w;
    }
    float iv = g_inv[w];
    acc.x *= iv; acc.y *= iv; acc.z *= iv; acc.w *= iv;
    ((float4*)(g_agg1 + w * HID))[lane] = acc;
}

// ---------------- layer-1 GEMM on tensor cores (tf32 mma.sync) ----------------
// h1 = agg1 @ wl.T + bl + h0 @ wr.T      [100k x 128] x [128 x 128] twice
// Block: 64 nodes x 128 channels, 256 thr = 8 warps (2 m-warps x 4 n-warps),
// warp tile 32x32 = 2 x 4 fragments of m16n8k8.
__device__ __forceinline__ uint32_t f2tf32(float f) {
    uint32_t u;
    asm("cvt.rna.tf32.f32 %0, %1;" : "=r"(u) : "f"(f));
    return u;
}

__device__ __forceinline__ void mma_tf32(float& c0, float& c1, float& c2, float& c3,
                                         uint32_t a0, uint32_t a1, uint32_t a2, uint32_t a3,
                                         uint32_t b0, uint32_t b1) {
    asm volatile(
        "mma.sync.aligned.m16n8k8.row.col.f32.tf32.tf32.f32 "
        "{%0,%1,%2,%3}, {%4,%5,%6,%7}, {%8,%9}, {%0,%1,%2,%3};"
        : "+f"(c0), "+f"(c1), "+f"(c2), "+f"(c3)
        : "r"(a0), "r"(a1), "r"(a2), "r"(a3), "r"(b0), "r"(b1));
}

#define ASTR 20   // row stride (floats) for As[64] / Ws[128]; 20 => conflict-free frags

__global__ void __launch_bounds__(256) k_gemm1_tc(const float* __restrict__ wl,
                                                  const float* __restrict__ bl,
                                                  const float* __restrict__ wr) {
    __shared__ float As[64 * ASTR];    // A tile, [m][k] m-major, tf32 bits
    __shared__ float Ws[128 * ASTR];   // W tile, [n][k]

    int tid  = threadIdx.x;
    int n0   = blockIdx.x * 64;
    int warp = tid >> 5, lane = tid & 31;
    int wm = (warp & 1) * 32;          // warp m-offset (0/32)
    int wn = (warp >> 1) * 32;         // warp n-offset (0/32/64/96)
    int gi = lane >> 2, ti = lane & 3; // fragment group/thread ids

    float c[2][4][4];
#pragma unroll
    for (int i = 0; i < 2; i++)
#pragma unroll
        for (int j = 0; j < 4; j++)
#pragma unroll
            for (int q = 0; q < 4; q++) c[i][j][q] = 0.0f;

    // staging indices
    int am = tid >> 2, ak = (tid & 3) * 4;     // A: node row, k4 chunk
    int wc = tid >> 1, wk = (tid & 1) * 8;     // W: channel row, k8 chunk
    int anode = n0 + am;

#pragma unroll 1
    for (int p = 0; p < 2; p++) {
        const float* A = p ? g_h0 : g_agg1;
        const float* W = p ? wr : wl;
#pragma unroll 1
        for (int kt = 0; kt < HID; kt += 16) {
            __syncthreads();
            // A tile 64x16
            {
                float4 v = make_float4(0.f, 0.f, 0.f, 0.f);
                if (anode < N_NODES) v = *(const float4*)(A + anode * HID + kt + ak);
                float4 t;
                t.x = __uint_as_float(f2tf32(v.x));
                t.y = __uint_as_float(f2tf32(v.y));
                t.z = __uint_as_float(f2tf32(v.z));
                t.w = __uint_as_float(f2tf32(v.w));
                *(float4*)&As[am * ASTR + ak] = t;
            }
            // W tile 128x16
            {
                const float4* wp = (const float4*)(W + wc * HID + kt + wk);
                float4 w0 = __ldg(wp), w1 = __ldg(wp + 1);
                float4 t0, t1;
                t0.x = __uint_as_float(f2tf32(w0.x));
                t0.y = __uint_as_float(f2tf32(w0.y));
                t0.z = __uint_as_float(f2tf32(w0.z));
                t0.w = __uint_as_float(f2tf32(w0.w));
                t1.x = __uint_as_float(f2tf32(w1.x));
                t1.y = __uint_as_float(f2tf32(w1.y));
                t1.z = __uint_as_float(f2tf32(w1.z));
                t1.w = __uint_as_float(f2tf32(w1.w));
                *(float4*)&Ws[wc * ASTR + wk]     = t0;
                *(float4*)&Ws[wc * ASTR + wk + 4] = t1;
            }
            __syncthreads();

#pragma unroll
            for (int kk = 0; kk < 16; kk += 8) {
                uint32_t a[2][4], b[4][2];
#pragma unroll
                for (int i = 0; i < 2; i++) {
                    int mb = wm + i * 16;
                    a[i][0] = __float_as_uint(As[(mb + gi)     * ASTR + kk + ti]);
                    a[i][1] = __float_as_uint(As[(mb + 8 + gi) * ASTR + kk + ti]);
                    a[i][2] = __float_as_uint(As[(mb + gi)     * ASTR + kk + 4 + ti]);
                    a[i][3] = __float_as_uint(As[(mb + 8 + gi) * ASTR + kk + 4 + ti]);
                }
#pragma unroll
                for (int j = 0; j < 4; j++) {
                    int nb = wn + j * 8;
                    b[j][0] = __float_as_uint(Ws[(nb + gi) * ASTR + kk + ti]);
                    b[j][1] = __float_as_uint(Ws[(nb + gi) * ASTR + kk + 4 + ti]);
                }
#pragma unroll
                for (int i = 0; i < 2; i++)
#pragma unroll
                    for (int j = 0; j < 4; j++)
                        mma_tf32(c[i][j][0], c[i][j][1], c[i][j][2], c[i][j][3],
                                 a[i][0], a[i][1], a[i][2], a[i][3],
                                 b[j][0], b[j][1]);
            }
        }
    }

    // epilogue: + bias, store to g_h1
#pragma unroll
    for (int i = 0; i < 2; i++) {
#pragma unroll
        for (int j = 0; j < 4; j++) {
            int ch = wn + j * 8 + ti * 2;
            float b0 = __ldg(&bl[ch]), b1 = __ldg(&bl[ch + 1]);
            int nodeA = n0 + wm + i * 16 + gi;
            int nodeB = nodeA + 8;
            if (nodeA < N_NODES) {
                float2 o = make_float2(c[i][j][0] + b0, c[i][j][1] + b1);
                *(float2*)(g_h1 + nodeA * HID + ch) = o;
            }
            if (nodeB < N_NODES) {
                float2 o = make_float2(c[i][j][2] + b0, c[i][j][3] + b1);
                *(float2*)(g_h1 + nodeB * HID + ch) = o;
            }
        }
    }
}

// ---------------- layer-2: project to scalars, then CSR-aggregate + sigmoid ----------------
__global__ void k_proj2(const float* __restrict__ wl2, const float* __restrict__ wr2) {
    int gt = blockIdx.x * blockDim.x + threadIdx.x;
    int n = gt >> 5;
    if (n >= N_NODES) return;
    int lane = threadIdx.x & 31;
    float4 h = ((const float4*)(g_h1 + n * HID))[lane];
    float4 a = __ldg((const float4*)wl2 + lane);
    float4 b = __ldg((const float4*)wr2 + lane);
    float pl = h.x * a.x + h.y * a.y + h.z * a.z + h.w * a.w;
    float pr = h.x * b.x + h.y * b.y + h.z * b.z + h.w * b.w;
#pragma unroll
    for (int o = 16; o > 0; o >>= 1) {
        pl += __shfl_xor_sync(0xffffffffu, pl, o);
        pr += __shfl_xor_sync(0xffffffffu, pr, o);
    }
    if (lane == 0) { g_pl[n] = pl; g_pr[n] = pr; }
}

__global__ void k_final(const float* __restrict__ bl2, float* __restrict__ out) {
    int n = blockIdx.x * blockDim.x + threadIdx.x;
    if (n >= N_NODES) return;
    int beg = g_off[n], end = g_off[n + 1];
    float a = 0.0f;
    for (int j = beg; j < end; j++) a += g_pl[g_esrc[j]];
    float z = a * g_inv[n] + __ldg(bl2) + g_pr[n];
    out[n] = 1.0f / (1.0f + expf(-z));
}

// ---------------- launch: kernel launches ONLY ----------------
extern "C" void kernel_launch(void* const* d_in, const int* in_sizes, int n_in,
                              void* d_out, int out_size) {
    const float* x   = (const float*)d_in[0];
    const int*   ei  = (const int*)d_in[1];   // int32 (JAX x64-disabled demotes int64)
    const float* wl0 = (const float*)d_in[2];
    const float* bl0 = (const float*)d_in[3];
    const float* wr0 = (const float*)d_in[4];
    const float* g0  = (const float*)d_in[5];
    const float* b0  = (const float*)d_in[6];
    const float* wl1 = (const float*)d_in[7];
    const float* bl1 = (const float*)d_in[8];
    const float* wr1 = (const float*)d_in[9];
    const float* g1  = (const float*)d_in[10];
    const float* b1  = (const float*)d_in[11];
    const float* wl2 = (const float*)d_in[12];
    const float* bl2 = (const float*)d_in[13];
    const float* wr2 = (const float*)d_in[14];
    float* out = (float*)d_out;

    k_zero <<<512, 256>>>();

    // CSR build
    k_count<<<(N_EDGES + 255) / 256, 256>>>(ei);
    k_scan1<<<SCAN_NB, SCAN_B>>>();
    k_scan2<<<1, 32>>>();
    k_scan3<<<SCAN_NB, SCAN_B>>>();
    k_fill <<<(N_EDGES + 255) / 256, 256>>>(ei);
    k_inv  <<<(N_NODES + 255) / 256, 256>>>();

    // layer 0
    k_agg0  <<<(N_NODES + 255) / 256, 256>>>(x);
    k_layer0<<<(N_NODES + 31) / 32, 128>>>(x, wl0, bl0, wr0);
    k_bnstats0<<<(N_NODES + 63) / 64, 128>>>();
    k_bnfinal <<<1, 128>>>(g0, b0);
    k_bnrelu0 <<<(N_NODES * (HID / 4) + 255) / 256, 256>>>();

    // layer 1
    k_agg1 <<<(N_NODES * 32 + 255) / 256, 256>>>();
    k_gemm1_tc<<<(N_NODES + 63) / 64, 256>>>(wl1, bl1, wr1);
    k_zero_bn <<<1, 128>>>();
    k_bnstats1<<<(N_NODES + 63) / 64, 128>>>();
    k_bnfinal <<<1, 128>>>(g1, b1);
    k_bnrelu1 <<<(N_NODES * (HID / 4) + 255) / 256, 256>>>();

    // layer 2
    k_proj2<<<(N_NODES * 32 + 255) / 256, 256>>>(wl2, wr2);
    k_final<<<(N_NODES + 255) / 256, 256>>>(bl2, out);
}